// round 10
// baseline (speedup 1.0000x reference)
#include <cuda_runtime.h>
#include <cstdint>
#include <math.h>

#define HIDDEN 1024
#define NH     16
#define HD     64
#define SEQ    2048
#define BATCH  2
#define MTOT   (BATCH*SEQ)   // 4096
#define WIN    128
#define QB     64

// ---------------- scratch (device globals) -------------------------------------
__device__ float g_Q[BATCH*NH*SEQ*HD];
__device__ float g_K[BATCH*NH*SEQ*HD];
__device__ float g_V[BATCH*NH*SEQ*HD];
__device__ float g_At[MTOT*HIDDEN];     // tf32-rounded activations
__device__ float g_Wq[HIDDEN*HIDDEN];   // tf32-rounded weights
__device__ float g_Wk[HIDDEN*HIDDEN];
__device__ float g_Wv[HIDDEN*HIDDEN];
__device__ float g_Wo[HIDDEN*HIDDEN];

// ---------------- helpers -------------------------------------------------------
__device__ __forceinline__ uint32_t smem_u32(const void* p) {
    uint32_t a;
    asm("{ .reg .u64 t; cvta.to.shared.u64 t, %1; cvt.u32.u64 %0, t; }" : "=r"(a) : "l"(p));
    return a;
}
__device__ __forceinline__ float tf32r(float x) {
    uint32_t y;
    asm("cvt.rna.tf32.f32 %0, %1;" : "=r"(y) : "f"(x));
    return __uint_as_float(y);
}
__device__ __forceinline__ void cp16(uint32_t dst, const float* src) {
    asm volatile("cp.async.cg.shared.global [%0], [%1], 16;" :: "r"(dst), "l"(src) : "memory");
}
__device__ __forceinline__ void cp16z(uint32_t dst, const float* src, int srcsz) {
    asm volatile("cp.async.cg.shared.global [%0], [%1], 16, %2;"
                 :: "r"(dst), "l"(src), "r"(srcsz) : "memory");
}
#define CP_COMMIT() asm volatile("cp.async.commit_group;" ::: "memory")
#define CP_WAIT2()  asm volatile("cp.async.wait_group 2;" ::: "memory")
#define CP_WAIT0()  asm volatile("cp.async.wait_group 0;" ::: "memory")

__device__ __forceinline__ void mma_tf32(float* d, const uint32_t* a, const uint32_t* b) {
    asm volatile("mma.sync.aligned.m16n8k8.row.col.f32.tf32.tf32.f32 "
        "{%0,%1,%2,%3}, {%4,%5,%6,%7}, {%8,%9}, {%0,%1,%2,%3};"
        : "+f"(d[0]), "+f"(d[1]), "+f"(d[2]), "+f"(d[3])
        : "r"(a[0]), "r"(a[1]), "r"(a[2]), "r"(a[3]), "r"(b[0]), "r"(b[1]));
}

// ---------------- tf32 GEMM: 128x256 tile, 512 threads, 64x32 warp tile ----------
#define BM 128
#define BN 256
#define BK 32
#define STAGES 4
#define AS_STRIDE 36
#define BS_STRIDE 260
#define A_STAGE (BM*AS_STRIDE)             // 4608
#define B_STAGE (BK*BS_STRIDE)             // 8320
#define STAGE_FLOATS (A_STAGE + B_STAGE)   // 12928
#define GEMM_SMEM (STAGES*STAGE_FLOATS*4)  // 206848 B (1 CTA/SM, 16 warps)

__global__ __launch_bounds__(512, 1) void gemm_mma_kernel(
    const float* __restrict__ A,
    const float* __restrict__ W0, const float* __restrict__ W1, const float* __restrict__ W2,
    const float* __restrict__ bias0, const float* __restrict__ bias1, const float* __restrict__ bias2,
    float* __restrict__ out0, float* __restrict__ out1, float* __restrict__ out2,
    int mode)
{
    extern __shared__ float sm[];
    const int tid  = threadIdx.x;
    const int lane = tid & 31;
    const int wid  = tid >> 5;          // 0..15
    const int n0 = blockIdx.x * BN;
    const int m0 = blockIdx.y * BM;
    const int z  = blockIdx.z;

    const float* W    = (z == 0) ? W0 : (z == 1) ? W1 : W2;
    const float* bias = (z == 0) ? bias0 : (z == 1) ? bias1 : bias2;
    float* out        = (z == 0) ? out0 : (z == 1) ? out1 : out2;

    const int wm = (wid & 1) * 64;      // 2 warp rows
    const int wn = (wid >> 1) * 32;     // 8 warp cols

    float d[4][4][4];
#pragma unroll
    for (int mi = 0; mi < 4; mi++)
#pragma unroll
        for (int ni = 0; ni < 4; ni++)
#pragma unroll
            for (int c = 0; c < 4; c++) d[mi][ni][c] = 0.f;

    const uint32_t sb = smem_u32(sm);

    auto load_stage = [&](int kt, int s) {
        const uint32_t a_off = sb + (uint32_t)(s * STAGE_FLOATS) * 4u;
        const uint32_t b_off = a_off + A_STAGE * 4u;
        const float* Ag = A + (long)m0 * HIDDEN + kt * BK;
        const float* Wg = W + (long)(kt * BK) * HIDDEN + n0;
#pragma unroll
        for (int rep = 0; rep < 2; rep++) {
            int lin = rep * 512 + tid;
            int ar = lin >> 3, aq = lin & 7;
            cp16(a_off + (uint32_t)(ar * AS_STRIDE + aq * 4) * 4u,
                 Ag + (long)ar * HIDDEN + aq * 4);
        }
#pragma unroll
        for (int rep = 0; rep < 4; rep++) {
            int lin = rep * 512 + tid;
            int br = lin >> 6, bq = lin & 63;
            cp16(b_off + (uint32_t)(br * BS_STRIDE + bq * 4) * 4u,
                 Wg + (long)br * HIDDEN + bq * 4);
        }
        CP_COMMIT();
    };

    load_stage(0, 0);
    load_stage(1, 1);
    load_stage(2, 2);

    const int lg = lane >> 2;
    const int lt = lane & 3;

    for (int kt = 0; kt < HIDDEN / BK; kt++) {
        const int s = kt & (STAGES - 1);
        CP_WAIT2();
        __syncthreads();
        if (kt + 3 < HIDDEN / BK) load_stage(kt + 3, (kt + 3) & (STAGES - 1));
        else CP_COMMIT();

        const float* As = sm + s * STAGE_FLOATS;
        const float* Bs = As + A_STAGE;

#pragma unroll
        for (int k8 = 0; k8 < 4; k8++) {
            const int kb = k8 * 8;
            uint32_t a[4][4];
#pragma unroll
            for (int mi = 0; mi < 4; mi++) {
                const float* ap = As + (wm + mi * 16 + lg) * AS_STRIDE + kb + lt;
                a[mi][0] = __float_as_uint(ap[0]);
                a[mi][1] = __float_as_uint(ap[8 * AS_STRIDE]);
                a[mi][2] = __float_as_uint(ap[4]);
                a[mi][3] = __float_as_uint(ap[8 * AS_STRIDE + 4]);
            }
#pragma unroll
            for (int ni = 0; ni < 4; ni++) {
                uint32_t bb[2];
                const float* bp = Bs + (kb + lt) * BS_STRIDE + wn + ni * 8 + lg;
                bb[0] = __float_as_uint(bp[0]);
                bb[1] = __float_as_uint(bp[4 * BS_STRIDE]);
#pragma unroll
                for (int mi = 0; mi < 4; mi++)
                    mma_tf32(d[mi][ni], a[mi], bb);
            }
        }
    }

#pragma unroll
    for (int mi = 0; mi < 4; mi++) {
#pragma unroll
        for (int rh = 0; rh < 2; rh++) {
            const int row = m0 + wm + mi * 16 + lg + rh * 8;
            const int bb = row >> 11;
            const int ss = row & (SEQ - 1);
#pragma unroll
            for (int ni = 0; ni < 4; ni++) {
                const int col = n0 + wn + ni * 8 + lt * 2;
                float2 v;
                v.x = d[mi][ni][rh * 2 + 0] + __ldg(&bias[col]);
                v.y = d[mi][ni][rh * 2 + 1] + __ldg(&bias[col + 1]);
                if (mode == 0) {
                    const int h  = col >> 6;
                    const int dd = col & 63;
                    *(float2*)&out[(((long)(bb * NH + h) * SEQ) + ss) * HD + dd] = v;
                } else {
                    *(float2*)&out[(long)row * HIDDEN + col] = v;
                }
            }
        }
    }
}

// ---------------- tf32 rounding kernels -------------------------------------------
__global__ void cvt_kernel(const float4* __restrict__ in, float4* __restrict__ out, int n4) {
    int i = blockIdx.x * blockDim.x + threadIdx.x;
    if (i < n4) {
        float4 v = in[i];
        v.x = tf32r(v.x); v.y = tf32r(v.y); v.z = tf32r(v.z); v.w = tf32r(v.w);
        out[i] = v;
    }
}
__global__ void cvtw_kernel(const float4* __restrict__ w0, const float4* __restrict__ w1,
                            const float4* __restrict__ w2, const float4* __restrict__ w3,
                            float4* __restrict__ o0, float4* __restrict__ o1,
                            float4* __restrict__ o2, float4* __restrict__ o3) {
    const int z = blockIdx.y;
    const float4* in = (z == 0) ? w0 : (z == 1) ? w1 : (z == 2) ? w2 : w3;
    float4* out      = (z == 0) ? o0 : (z == 1) ? o1 : (z == 2) ? o2 : o3;
    int i = blockIdx.x * blockDim.x + threadIdx.x;
    float4 v = in[i];
    v.x = tf32r(v.x); v.y = tf32r(v.y); v.z = tf32r(v.z); v.w = tf32r(v.w);
    out[i] = v;
}

// ---------------- chunked attention (unchanged from R9) ---------------------------
#define CH   160
#define SQ   68
#define SKN  68
#define SVC  72
#define SPC  164
#define SO   66
#define QS_OFF  0
#define KS_OFF  4352
#define VS_OFF  (KS_OFF + CH*SKN)
#define RED_OFF (VS_OFF + CH*SVC)
#define ATTN_FLOATS (RED_OFF + 128)
#define ATTN_SMEM (ATTN_FLOATS * 4)

__global__ __launch_bounds__(256, 2) void attn_mma_kernel(
    const float* __restrict__ Q, const float* __restrict__ K,
    const float* __restrict__ V, float* __restrict__ O)
{
    extern __shared__ float sm[];
    float* Qs = sm + QS_OFF;
    float* Ks = sm + KS_OFF;
    float* Vs = sm + VS_OFF;
    float* red = sm + RED_OFF;

    const int q0 = blockIdx.x * QB;
    const int h  = blockIdx.y;
    const int b  = blockIdx.z;
    const int tid = threadIdx.x;
    const long base = ((long)(b * NH + h)) * SEQ * HD;
    const float* Kb = K + base;
    const float* Vb = V + base;
    const float* Qb = Q + base;
    const int j0 = q0 - WIN;

    const uint32_t sb = smem_u32(sm);
    const int lane = tid & 31;
    const int wid  = tid >> 5;
    const int lg = lane >> 2;
    const int lt = lane & 3;
    const int wm = (wid & 3) * 16;
    const int half = wid >> 2;
    const int wn = half * 80;
    const float scale = 0.125f;

    for (int idx = tid; idx < 64 * 16; idx += 256) {
        int r = idx >> 4, c4 = (idx & 15) << 2;
        float4 v = *(const float4*)&Qb[(long)(q0 + r) * HD + c4];
        v.x = tf32r(v.x); v.y = tf32r(v.y); v.z = tf32r(v.z); v.w = tf32r(v.w);
        *(float4*)&Qs[r * SQ + c4] = v;
    }

    float o[8][4];
#pragma unroll
    for (int nt = 0; nt < 8; nt++) { o[nt][0] = 0.f; o[nt][1] = 0.f; o[nt][2] = 0.f; o[nt][3] = 0.f; }
    float sum0 = 0.f, sum1 = 0.f;

    const int r0 = q0 + wm + lg;
    const int r1 = r0 + 8;
    const int lo0 = ((r0 - WIN > 0) ? r0 - WIN : 0) - j0;
    const int hi0 = ((r0 + WIN < SEQ - 1) ? r0 + WIN : SEQ - 1) - j0;
    const int lo1 = ((r1 - WIN > 0) ? r1 - WIN : 0) - j0;
    const int hi1 = ((r1 + WIN < SEQ - 1) ? r1 + WIN : SEQ - 1) - j0;

    uint32_t a[8][4];
    bool afrag_loaded = false;

#pragma unroll
    for (int ch = 0; ch < 2; ch++) {
        const int cb = ch * CH;

        {
            const int rb = tid >> 4;
            const int cq = (tid & 15) << 2;
#pragma unroll
            for (int r10 = 0; r10 < 10; r10++) {
                const int jj = r10 * 16 + rb;
                const int j  = j0 + cb + jj;
                const int ok = (j >= 0 && j < SEQ) ? 16 : 0;
                cp16z(sb + (uint32_t)(KS_OFF + jj * SKN + cq) * 4u, Kb + (long)j * HD + cq, ok);
                cp16z(sb + (uint32_t)(VS_OFF + jj * SVC + cq) * 4u, Vb + (long)j * HD + cq, ok);
            }
            CP_COMMIT();
        }
        CP_WAIT0();
        __syncthreads();

        if (!afrag_loaded) {
            afrag_loaded = true;
#pragma unroll
            for (int k8 = 0; k8 < 8; k8++) {
                const float* ap = Qs + (wm + lg) * SQ + k8 * 8 + lt;
                a[k8][0] = __float_as_uint(ap[0]);
                a[k8][1] = __float_as_uint(ap[8 * SQ]);
                a[k8][2] = __float_as_uint(ap[4]);
                a[k8][3] = __float_as_uint(ap[8 * SQ + 4]);
            }
        }

        float c[10][4];
#pragma unroll
        for (int nt = 0; nt < 10; nt++) {
            c[nt][0] = 0.f; c[nt][1] = 0.f; c[nt][2] = 0.f; c[nt][3] = 0.f;
            const int key = wn + nt * 8 + lg;
            const float* kp = Ks + key * SKN + lt;
#pragma unroll
            for (int k8 = 0; k8 < 8; k8++) {
                uint32_t bb[2];
                bb[0] = __float_as_uint(tf32r(kp[k8 * 8]));
                bb[1] = __float_as_uint(tf32r(kp[k8 * 8 + 4]));
                mma_tf32(c[nt], a[k8], bb);
            }
        }

#pragma unroll
        for (int nt = 0; nt < 10; nt++) {
            const int jw = cb + wn + nt * 8 + 2 * lt;
            float p0 = (jw     >= lo0 && jw     <= hi0) ? tf32r(__expf(c[nt][0] * scale)) : 0.f;
            float p1 = (jw + 1 >= lo0 && jw + 1 <= hi0) ? tf32r(__expf(c[nt][1] * scale)) : 0.f;
            float p2 = (jw     >= lo1 && jw     <= hi1) ? tf32r(__expf(c[nt][2] * scale)) : 0.f;
            float p3 = (jw + 1 >= lo1 && jw + 1 <= hi1) ? tf32r(__expf(c[nt][3] * scale)) : 0.f;
            c[nt][0] = p0; c[nt][1] = p1; c[nt][2] = p2; c[nt][3] = p3;
            sum0 += p0 + p1;
            sum1 += p2 + p3;
        }

        __syncthreads();

        float* Ps = Ks;
#pragma unroll
        for (int nt = 0; nt < 10; nt++) {
            const int col = wn + nt * 8 + 2 * lt;
            *(float2*)&Ps[(wm + lg) * SPC + col]     = make_float2(c[nt][0], c[nt][1]);
            *(float2*)&Ps[(wm + lg + 8) * SPC + col] = make_float2(c[nt][2], c[nt][3]);
        }
        __syncthreads();

#pragma unroll
        for (int k8 = 0; k8 < 10; k8++) {
            const int kk = wn + k8 * 8;
            uint32_t a2[4];
            const float* ap = Ps + (wm + lg) * SPC + kk + lt;
            a2[0] = __float_as_uint(ap[0]);
            a2[1] = __float_as_uint(ap[8 * SPC]);
            a2[2] = __float_as_uint(ap[4]);
            a2[3] = __float_as_uint(ap[8 * SPC + 4]);
#pragma unroll
            for (int nt = 0; nt < 8; nt++) {
                uint32_t bb[2];
                const float* bp = Vs + (kk + lt) * SVC + nt * 8 + lg;
                bb[0] = __float_as_uint(bp[0]);
                bb[1] = __float_as_uint(bp[4 * SVC]);
                mma_tf32(o[nt], a2, bb);
            }
        }
        __syncthreads();
    }

    sum0 += __shfl_xor_sync(0xffffffffu, sum0, 1);
    sum0 += __shfl_xor_sync(0xffffffffu, sum0, 2);
    sum1 += __shfl_xor_sync(0xffffffffu, sum1, 1);
    sum1 += __shfl_xor_sync(0xffffffffu, sum1, 2);
    if (lt == 0) {
        red[half * 64 + wm + lg]     = sum0;
        red[half * 64 + wm + lg + 8] = sum1;
    }

    float* obuf = Qs;
    if (half == 0) {
#pragma unroll
        for (int nt = 0; nt < 8; nt++) {
            const int col = nt * 8 + 2 * lt;
            *(float2*)&obuf[(wm + lg) * SO + col]     = make_float2(o[nt][0], o[nt][1]);
            *(float2*)&obuf[(wm + lg + 8) * SO + col] = make_float2(o[nt][2], o[nt][3]);
        }
    }
    __syncthreads();
    if (half == 1) {
        const float inv0 = 1.f / (red[wm + lg] + red[64 + wm + lg]);
        const float inv1 = 1.f / (red[wm + lg + 8] + red[64 + wm + lg + 8]);
        const long ob0 = ((long)(b * SEQ + r0)) * HIDDEN + h * HD;
        const long ob1 = ((long)(b * SEQ + r1)) * HIDDEN + h * HD;
#pragma unroll
        for (int nt = 0; nt < 8; nt++) {
            const int col = nt * 8 + 2 * lt;
            float2 u0 = *(const float2*)&obuf[(wm + lg) * SO + col];
            float2 u1 = *(const float2*)&obuf[(wm + lg + 8) * SO + col];
            float2 w0, w1;
            w0.x = tf32r((o[nt][0] + u0.x) * inv0);
            w0.y = tf32r((o[nt][1] + u0.y) * inv0);
            w1.x = tf32r((o[nt][2] + u1.x) * inv1);
            w1.y = tf32r((o[nt][3] + u1.y) * inv1);
            *(float2*)&O[ob0 + col] = w0;
            *(float2*)&O[ob1 + col] = w1;
        }
    }
}

// ---------------- launcher --------------------------------------------------------
extern "C" void kernel_launch(void* const* d_in, const int* in_sizes, int n_in,
                              void* d_out, int out_size)
{
    const float* x  = (const float*)d_in[0];
    const float* wq = (const float*)d_in[1];
    const float* bq = (const float*)d_in[2];
    const float* wk = (const float*)d_in[3];
    const float* bk = (const float*)d_in[4];
    const float* wv = (const float*)d_in[5];
    const float* bv = (const float*)d_in[6];
    const float* wo = (const float*)d_in[7];
    const float* bo = (const float*)d_in[8];

    float *gq, *gk, *gv, *gat, *gwq, *gwk, *gwv, *gwo;
    cudaGetSymbolAddress((void**)&gq,  g_Q);
    cudaGetSymbolAddress((void**)&gk,  g_K);
    cudaGetSymbolAddress((void**)&gv,  g_V);
    cudaGetSymbolAddress((void**)&gat, g_At);
    cudaGetSymbolAddress((void**)&gwq, g_Wq);
    cudaGetSymbolAddress((void**)&gwk, g_Wk);
    cudaGetSymbolAddress((void**)&gwv, g_Wv);
    cudaGetSymbolAddress((void**)&gwo, g_Wo);

    cudaFuncSetAttribute(gemm_mma_kernel,
                         cudaFuncAttributeMaxDynamicSharedMemorySize, GEMM_SMEM);
    cudaFuncSetAttribute(attn_mma_kernel,
                         cudaFuncAttributeMaxDynamicSharedMemorySize, ATTN_SMEM);

    const int n4a = MTOT * HIDDEN / 4;
    const int n4w = HIDDEN * HIDDEN / 4;

    cvt_kernel<<<(n4a + 255) / 256, 256>>>((const float4*)x, (float4*)gat, n4a);
    {
        dim3 g(n4w / 256, 4);
        cvtw_kernel<<<g, 256>>>((const float4*)wq, (const float4*)wk,
                                (const float4*)wv, (const float4*)wo,
                                (float4*)gwq, (float4*)gwk, (float4*)gwv, (float4*)gwo);
    }
    {   // fused QKV projections (512 threads/CTA)
        dim3 g(HIDDEN / BN, MTOT / BM, 3);
        gemm_mma_kernel<<<g, 512, GEMM_SMEM>>>(gat, gwq, gwk, gwv,
                                               bq, bk, bv, gq, gk, gv, 0);
    }
    {   // chunked MMA attention -> tf32-rounded output into g_At
        dim3 ga(SEQ / QB, NH, BATCH);
        attn_mma_kernel<<<ga, 256, ATTN_SMEM>>>(gq, gk, gv, gat);
    }
    {   // output projection
        dim3 g(HIDDEN / BN, MTOT / BM, 1);
        gemm_mma_kernel<<<g, 512, GEMM_SMEM>>>(gat, gwo, gwo, gwo,
                                               bo, bo, bo, (float*)d_out,
                                               (float*)d_out, (float*)d_out, 1);
    }
}

// round 12
// speedup vs baseline: 1.0800x; 1.0800x over previous
#include <cuda_runtime.h>
#include <cstdint>
#include <math.h>

#define HIDDEN 1024
#define NH     16
#define HD     64
#define SEQ    2048
#define BATCH  2
#define MTOT   (BATCH*SEQ)   // 4096
#define WIN    128
#define QB     64

// ---------------- scratch (device globals) -------------------------------------
__device__ float g_Q[BATCH*NH*SEQ*HD];
__device__ float g_K[BATCH*NH*SEQ*HD];
__device__ float g_V[BATCH*NH*SEQ*HD];
__device__ float g_At[MTOT*HIDDEN];     // tf32-rounded activations
__device__ float g_Wq[HIDDEN*HIDDEN];   // tf32-rounded weights
__device__ float g_Wk[HIDDEN*HIDDEN];
__device__ float g_Wv[HIDDEN*HIDDEN];
__device__ float g_Wo[HIDDEN*HIDDEN];

// ---------------- helpers -------------------------------------------------------
__device__ __forceinline__ uint32_t smem_u32(const void* p) {
    uint32_t a;
    asm("{ .reg .u64 t; cvta.to.shared.u64 t, %1; cvt.u32.u64 %0, t; }" : "=r"(a) : "l"(p));
    return a;
}
__device__ __forceinline__ float tf32r(float x) {
    uint32_t y;
    asm("cvt.rna.tf32.f32 %0, %1;" : "=r"(y) : "f"(x));
    return __uint_as_float(y);
}
__device__ __forceinline__ void cp16(uint32_t dst, const float* src) {
    asm volatile("cp.async.cg.shared.global [%0], [%1], 16;" :: "r"(dst), "l"(src) : "memory");
}
__device__ __forceinline__ void cp16z(uint32_t dst, const float* src, int srcsz) {
    asm volatile("cp.async.cg.shared.global [%0], [%1], 16, %2;"
                 :: "r"(dst), "l"(src), "r"(srcsz) : "memory");
}
#define CP_COMMIT() asm volatile("cp.async.commit_group;" ::: "memory")
#define CP_WAIT2()  asm volatile("cp.async.wait_group 2;" ::: "memory")
#define CP_WAIT0()  asm volatile("cp.async.wait_group 0;" ::: "memory")

__device__ __forceinline__ void mma_tf32(float* d, const uint32_t* a, const uint32_t* b) {
    asm volatile("mma.sync.aligned.m16n8k8.row.col.f32.tf32.tf32.f32 "
        "{%0,%1,%2,%3}, {%4,%5,%6,%7}, {%8,%9}, {%0,%1,%2,%3};"
        : "+f"(d[0]), "+f"(d[1]), "+f"(d[2]), "+f"(d[3])
        : "r"(a[0]), "r"(a[1]), "r"(a[2]), "r"(a[3]), "r"(b[0]), "r"(b[1]));
}

// ---------------- tf32 GEMM: 128x256 tile, 256 thr, 64x64 warp tile (R9 cfg) -----
#define BM 128
#define BN 256
#define BK 32
#define STAGES 4
#define AS_STRIDE 36
#define BS_STRIDE 260
#define A_STAGE (BM*AS_STRIDE)             // 4608
#define B_STAGE (BK*BS_STRIDE)             // 8320
#define STAGE_FLOATS (A_STAGE + B_STAGE)   // 12928
#define GEMM_SMEM (STAGES*STAGE_FLOATS*4)  // 206848 B

__global__ __launch_bounds__(256, 1) void gemm_mma_kernel(
    const float* __restrict__ A,
    const float* __restrict__ W0, const float* __restrict__ W1, const float* __restrict__ W2,
    const float* __restrict__ bias0, const float* __restrict__ bias1, const float* __restrict__ bias2,
    float* __restrict__ out0, float* __restrict__ out1, float* __restrict__ out2,
    int mode)
{
    extern __shared__ float sm[];
    const int tid  = threadIdx.x;
    const int lane = tid & 31;
    const int wid  = tid >> 5;
    const int n0 = blockIdx.x * BN;
    const int m0 = blockIdx.y * BM;
    const int z  = blockIdx.z;

    const float* W    = (z == 0) ? W0 : (z == 1) ? W1 : W2;
    const float* bias = (z == 0) ? bias0 : (z == 1) ? bias1 : bias2;
    float* out        = (z == 0) ? out0 : (z == 1) ? out1 : out2;

    const int wm = (wid & 1) * 64;
    const int wn = (wid >> 1) * 64;

    float d[4][8][4];
#pragma unroll
    for (int mi = 0; mi < 4; mi++)
#pragma unroll
        for (int ni = 0; ni < 8; ni++)
#pragma unroll
            for (int c = 0; c < 4; c++) d[mi][ni][c] = 0.f;

    const uint32_t sb = smem_u32(sm);

    auto load_stage = [&](int kt, int s) {
        const uint32_t a_off = sb + (uint32_t)(s * STAGE_FLOATS) * 4u;
        const uint32_t b_off = a_off + A_STAGE * 4u;
        const float* Ag = A + (long)m0 * HIDDEN + kt * BK;
        const float* Wg = W + (long)(kt * BK) * HIDDEN + n0;
#pragma unroll
        for (int rep = 0; rep < 4; rep++) {
            int lin = rep * 256 + tid;
            int ar = lin >> 3, aq = lin & 7;
            cp16(a_off + (uint32_t)(ar * AS_STRIDE + aq * 4) * 4u,
                 Ag + (long)ar * HIDDEN + aq * 4);
        }
#pragma unroll
        for (int rep = 0; rep < 8; rep++) {
            int lin = rep * 256 + tid;
            int br = lin >> 6, bq = lin & 63;
            cp16(b_off + (uint32_t)(br * BS_STRIDE + bq * 4) * 4u,
                 Wg + (long)br * HIDDEN + bq * 4);
        }
        CP_COMMIT();
    };

    load_stage(0, 0);
    load_stage(1, 1);
    load_stage(2, 2);

    const int lg = lane >> 2;
    const int lt = lane & 3;

    for (int kt = 0; kt < HIDDEN / BK; kt++) {
        const int s = kt & (STAGES - 1);
        CP_WAIT2();
        __syncthreads();
        if (kt + 3 < HIDDEN / BK) load_stage(kt + 3, (kt + 3) & (STAGES - 1));
        else CP_COMMIT();

        const float* As = sm + s * STAGE_FLOATS;
        const float* Bs = As + A_STAGE;

#pragma unroll
        for (int k8 = 0; k8 < 4; k8++) {
            const int kb = k8 * 8;
            uint32_t a[4][4];
#pragma unroll
            for (int mi = 0; mi < 4; mi++) {
                const float* ap = As + (wm + mi * 16 + lg) * AS_STRIDE + kb + lt;
                a[mi][0] = __float_as_uint(ap[0]);
                a[mi][1] = __float_as_uint(ap[8 * AS_STRIDE]);
                a[mi][2] = __float_as_uint(ap[4]);
                a[mi][3] = __float_as_uint(ap[8 * AS_STRIDE + 4]);
            }
#pragma unroll
            for (int ni = 0; ni < 8; ni++) {
                uint32_t bb[2];
                const float* bp = Bs + (kb + lt) * BS_STRIDE + wn + ni * 8 + lg;
                bb[0] = __float_as_uint(bp[0]);
                bb[1] = __float_as_uint(bp[4 * BS_STRIDE]);
#pragma unroll
                for (int mi = 0; mi < 4; mi++)
                    mma_tf32(d[mi][ni], a[mi], bb);
            }
        }
    }

    // epilogue: mode 0 writes rna-rounded Q/K/V (attention consumes them raw)
#pragma unroll
    for (int mi = 0; mi < 4; mi++) {
#pragma unroll
        for (int rh = 0; rh < 2; rh++) {
            const int row = m0 + wm + mi * 16 + lg + rh * 8;
            const int bb = row >> 11;
            const int ss = row & (SEQ - 1);
#pragma unroll
            for (int ni = 0; ni < 8; ni++) {
                const int col = n0 + wn + ni * 8 + lt * 2;
                float2 v;
                v.x = d[mi][ni][rh * 2 + 0] + __ldg(&bias[col]);
                v.y = d[mi][ni][rh * 2 + 1] + __ldg(&bias[col + 1]);
                if (mode == 0) {
                    v.x = tf32r(v.x);
                    v.y = tf32r(v.y);
                    const int h  = col >> 6;
                    const int dd = col & 63;
                    *(float2*)&out[(((long)(bb * NH + h) * SEQ) + ss) * HD + dd] = v;
                } else {
                    *(float2*)&out[(long)row * HIDDEN + col] = v;
                }
            }
        }
    }
}

// ---------------- tf32 rounding kernels -------------------------------------------
__global__ void cvt_kernel(const float4* __restrict__ in, float4* __restrict__ out, int n4) {
    int i = blockIdx.x * blockDim.x + threadIdx.x;
    if (i < n4) {
        float4 v = in[i];
        v.x = tf32r(v.x); v.y = tf32r(v.y); v.z = tf32r(v.z); v.w = tf32r(v.w);
        out[i] = v;
    }
}
__global__ void cvtw_kernel(const float4* __restrict__ w0, const float4* __restrict__ w1,
                            const float4* __restrict__ w2, const float4* __restrict__ w3,
                            float4* __restrict__ o0, float4* __restrict__ o1,
                            float4* __restrict__ o2, float4* __restrict__ o3) {
    const int z = blockIdx.y;
    const float4* in = (z == 0) ? w0 : (z == 1) ? w1 : (z == 2) ? w2 : w3;
    float4* out      = (z == 0) ? o0 : (z == 1) ? o1 : (z == 2) ? o2 : o3;
    int i = blockIdx.x * blockDim.x + threadIdx.x;
    float4 v = in[i];
    v.x = tf32r(v.x); v.y = tf32r(v.y); v.z = tf32r(v.z); v.w = tf32r(v.w);
    out[i] = v;
}

// ---------------- chunked attention: inputs pre-rounded, zero hot-loop cvt --------
#define CH   160
#define SQ   68
#define SKN  68
#define SVC  72
#define SPC  164
#define SO   66
#define QS_OFF  0
#define KS_OFF  4352
#define VS_OFF  (KS_OFF + CH*SKN)
#define RED_OFF (VS_OFF + CH*SVC)
#define ATTN_FLOATS (RED_OFF + 128)
#define ATTN_SMEM (ATTN_FLOATS * 4)

__global__ __launch_bounds__(256, 2) void attn_mma_kernel(
    const float* __restrict__ Q, const float* __restrict__ K,
    const float* __restrict__ V, float* __restrict__ O)
{
    extern __shared__ float sm[];
    float* Qs = sm + QS_OFF;
    float* Ks = sm + KS_OFF;
    float* Vs = sm + VS_OFF;
    float* red = sm + RED_OFF;

    const int q0 = blockIdx.x * QB;
    const int h  = blockIdx.y;
    const int b  = blockIdx.z;
    const int tid = threadIdx.x;
    const long base = ((long)(b * NH + h)) * SEQ * HD;
    const float* Kb = K + base;
    const float* Vb = V + base;
    const float* Qb = Q + base;
    const int j0 = q0 - WIN;

    const uint32_t sb = smem_u32(sm);
    const int lane = tid & 31;
    const int wid  = tid >> 5;
    const int lg = lane >> 2;
    const int lt = lane & 3;
    const int wm = (wid & 3) * 16;
    const int half = wid >> 2;
    const int wn = half * 80;
    const float scale = 0.125f;

    // Q tile (pre-rounded by QKV epilogue) via cp.async: 64 rows x 16 quads
    {
#pragma unroll
        for (int rep = 0; rep < 4; rep++) {
            const int idx = rep * 256 + tid;     // 0..1023
            const int r = idx >> 4;              // 0..63
            const int q = idx & 15;              // quad 0..15
            cp16(sb + (uint32_t)(QS_OFF + r * SQ + q * 4) * 4u,
                 Qb + (long)(q0 + r) * HD + q * 4);
        }
        CP_COMMIT();
    }

    float o[8][4];
#pragma unroll
    for (int nt = 0; nt < 8; nt++) { o[nt][0] = 0.f; o[nt][1] = 0.f; o[nt][2] = 0.f; o[nt][3] = 0.f; }
    float sum0 = 0.f, sum1 = 0.f;

    const int r0 = q0 + wm + lg;
    const int r1 = r0 + 8;
    const int lo0 = ((r0 - WIN > 0) ? r0 - WIN : 0) - j0;
    const int hi0 = ((r0 + WIN < SEQ - 1) ? r0 + WIN : SEQ - 1) - j0;
    const int lo1 = ((r1 - WIN > 0) ? r1 - WIN : 0) - j0;
    const int hi1 = ((r1 + WIN < SEQ - 1) ? r1 + WIN : SEQ - 1) - j0;

    uint32_t a[8][4];
    bool afrag_loaded = false;

#pragma unroll
    for (int ch = 0; ch < 2; ch++) {
        const int cb = ch * CH;

        {
            const int rb = tid >> 4;
            const int cq = (tid & 15) << 2;
#pragma unroll
            for (int r10 = 0; r10 < 10; r10++) {
                const int jj = r10 * 16 + rb;
                const int j  = j0 + cb + jj;
                const int ok = (j >= 0 && j < SEQ) ? 16 : 0;
                cp16z(sb + (uint32_t)(KS_OFF + jj * SKN + cq) * 4u, Kb + (long)j * HD + cq, ok);
                cp16z(sb + (uint32_t)(VS_OFF + jj * SVC + cq) * 4u, Vb + (long)j * HD + cq, ok);
            }
            CP_COMMIT();
        }
        CP_WAIT0();
        __syncthreads();

        if (!afrag_loaded) {
            afrag_loaded = true;
#pragma unroll
            for (int k8 = 0; k8 < 8; k8++) {
                const float* ap = Qs + (wm + lg) * SQ + k8 * 8 + lt;
                a[k8][0] = __float_as_uint(ap[0]);
                a[k8][1] = __float_as_uint(ap[8 * SQ]);
                a[k8][2] = __float_as_uint(ap[4]);
                a[k8][3] = __float_as_uint(ap[8 * SQ + 4]);
            }
        }

        float c[10][4];
#pragma unroll
        for (int nt = 0; nt < 10; nt++) {
            c[nt][0] = 0.f; c[nt][1] = 0.f; c[nt][2] = 0.f; c[nt][3] = 0.f;
            const int key = wn + nt * 8 + lg;
            const float* kp = Ks + key * SKN + lt;
#pragma unroll
            for (int k8 = 0; k8 < 8; k8++) {
                uint32_t bb[2];
                bb[0] = __float_as_uint(kp[k8 * 8]);
                bb[1] = __float_as_uint(kp[k8 * 8 + 4]);
                mma_tf32(c[nt], a[k8], bb);
            }
        }

#pragma unroll
        for (int nt = 0; nt < 10; nt++) {
            const int jw = cb + wn + nt * 8 + 2 * lt;
            float p0 = (jw     >= lo0 && jw     <= hi0) ? tf32r(__expf(c[nt][0] * scale)) : 0.f;
            float p1 = (jw + 1 >= lo0 && jw + 1 <= hi0) ? tf32r(__expf(c[nt][1] * scale)) : 0.f;
            float p2 = (jw     >= lo1 && jw     <= hi1) ? tf32r(__expf(c[nt][2] * scale)) : 0.f;
            float p3 = (jw + 1 >= lo1 && jw + 1 <= hi1) ? tf32r(__expf(c[nt][3] * scale)) : 0.f;
            c[nt][0] = p0; c[nt][1] = p1; c[nt][2] = p2; c[nt][3] = p3;
            sum0 += p0 + p1;
            sum1 += p2 + p3;
        }

        __syncthreads();

        float* Ps = Ks;
#pragma unroll
        for (int nt = 0; nt < 10; nt++) {
            const int col = wn + nt * 8 + 2 * lt;
            *(float2*)&Ps[(wm + lg) * SPC + col]     = make_float2(c[nt][0], c[nt][1]);
            *(float2*)&Ps[(wm + lg + 8) * SPC + col] = make_float2(c[nt][2], c[nt][3]);
        }
        __syncthreads();

#pragma unroll
        for (int k8 = 0; k8 < 10; k8++) {
            const int kk = wn + k8 * 8;
            uint32_t a2[4];
            const float* ap = Ps + (wm + lg) * SPC + kk + lt;
            a2[0] = __float_as_uint(ap[0]);
            a2[1] = __float_as_uint(ap[8 * SPC]);
            a2[2] = __float_as_uint(ap[4]);
            a2[3] = __float_as_uint(ap[8 * SPC + 4]);
#pragma unroll
            for (int nt = 0; nt < 8; nt++) {
                uint32_t bb[2];
                const float* bp = Vs + (kk + lt) * SVC + nt * 8 + lg;
                bb[0] = __float_as_uint(bp[0]);
                bb[1] = __float_as_uint(bp[4 * SVC]);
                mma_tf32(o[nt], a2, bb);
            }
        }
        __syncthreads();
    }

    sum0 += __shfl_xor_sync(0xffffffffu, sum0, 1);
    sum0 += __shfl_xor_sync(0xffffffffu, sum0, 2);
    sum1 += __shfl_xor_sync(0xffffffffu, sum1, 1);
    sum1 += __shfl_xor_sync(0xffffffffu, sum1, 2);
    if (lt == 0) {
        red[half * 64 + wm + lg]     = sum0;
        red[half * 64 + wm + lg + 8] = sum1;
    }

    float* obuf = Qs;
    if (half == 0) {
#pragma unroll
        for (int nt = 0; nt < 8; nt++) {
            const int col = nt * 8 + 2 * lt;
            *(float2*)&obuf[(wm + lg) * SO + col]     = make_float2(o[nt][0], o[nt][1]);
            *(float2*)&obuf[(wm + lg + 8) * SO + col] = make_float2(o[nt][2], o[nt][3]);
        }
    }
    __syncthreads();
    if (half == 1) {
        const float inv0 = 1.f / (red[wm + lg] + red[64 + wm + lg]);
        const float inv1 = 1.f / (red[wm + lg + 8] + red[64 + wm + lg + 8]);
        const long ob0 = ((long)(b * SEQ + r0)) * HIDDEN + h * HD;
        const long ob1 = ((long)(b * SEQ + r1)) * HIDDEN + h * HD;
#pragma unroll
        for (int nt = 0; nt < 8; nt++) {
            const int col = nt * 8 + 2 * lt;
            float2 u0 = *(const float2*)&obuf[(wm + lg) * SO + col];
            float2 u1 = *(const float2*)&obuf[(wm + lg + 8) * SO + col];
            float2 w0, w1;
            w0.x = tf32r((o[nt][0] + u0.x) * inv0);
            w0.y = tf32r((o[nt][1] + u0.y) * inv0);
            w1.x = tf32r((o[nt][2] + u1.x) * inv1);
            w1.y = tf32r((o[nt][3] + u1.y) * inv1);
            *(float2*)&O[ob0 + col] = w0;
            *(float2*)&O[ob1 + col] = w1;
        }
    }
}

// ---------------- launcher --------------------------------------------------------
extern "C" void kernel_launch(void* const* d_in, const int* in_sizes, int n_in,
                              void* d_out, int out_size)
{
    const float* x  = (const float*)d_in[0];
    const float* wq = (const float*)d_in[1];
    const float* bq = (const float*)d_in[2];
    const float* wk = (const float*)d_in[3];
    const float* bk = (const float*)d_in[4];
    const float* wv = (const float*)d_in[5];
    const float* bv = (const float*)d_in[6];
    const float* wo = (const float*)d_in[7];
    const float* bo = (const float*)d_in[8];

    float *gq, *gk, *gv, *gat, *gwq, *gwk, *gwv, *gwo;
    cudaGetSymbolAddress((void**)&gq,  g_Q);
    cudaGetSymbolAddress((void**)&gk,  g_K);
    cudaGetSymbolAddress((void**)&gv,  g_V);
    cudaGetSymbolAddress((void**)&gat, g_At);
    cudaGetSymbolAddress((void**)&gwq, g_Wq);
    cudaGetSymbolAddress((void**)&gwk, g_Wk);
    cudaGetSymbolAddress((void**)&gwv, g_Wv);
    cudaGetSymbolAddress((void**)&gwo, g_Wo);

    cudaFuncSetAttribute(gemm_mma_kernel,
                         cudaFuncAttributeMaxDynamicSharedMemorySize, GEMM_SMEM);
    cudaFuncSetAttribute(attn_mma_kernel,
                         cudaFuncAttributeMaxDynamicSharedMemorySize, ATTN_SMEM);

    const int n4a = MTOT * HIDDEN / 4;
    const int n4w = HIDDEN * HIDDEN / 4;

    cvt_kernel<<<(n4a + 255) / 256, 256>>>((const float4*)x, (float4*)gat, n4a);
    {
        dim3 g(n4w / 256, 4);
        cvtw_kernel<<<g, 256>>>((const float4*)wq, (const float4*)wk,
                                (const float4*)wv, (const float4*)wo,
                                (float4*)gwq, (float4*)gwk, (float4*)gwv, (float4*)gwo);
    }
    {   // fused QKV projections (R9 config; epilogue rounds Q/K/V)
        dim3 g(HIDDEN / BN, MTOT / BM, 3);
        gemm_mma_kernel<<<g, 256, GEMM_SMEM>>>(gat, gwq, gwk, gwv,
                                               bq, bk, bv, gq, gk, gv, 0);
    }
    {   // chunked MMA attention (no hot-loop cvt) -> rounded output into g_At
        dim3 ga(SEQ / QB, NH, BATCH);
        attn_mma_kernel<<<ga, 256, ATTN_SMEM>>>(gq, gk, gv, gat);
    }
    {   // output projection
        dim3 g(HIDDEN / BN, MTOT / BM, 1);
        gemm_mma_kernel<<<g, 256, GEMM_SMEM>>>(gat, gwo, gwo, gwo,
                                               bo, bo, bo, (float*)d_out,
                                               (float*)d_out, (float*)d_out, 1);
    }
}

// round 13
// speedup vs baseline: 1.5323x; 1.4189x over previous
#include <cuda_runtime.h>
#include <cuda_fp16.h>
#include <cstdint>
#include <math.h>

#define HIDDEN 1024
#define NH     16
#define HD     64
#define SEQ    2048
#define BATCH  2
#define MTOT   (BATCH*SEQ)   // 4096
#define WIN    128
#define QB     64

// ---------------- scratch (device globals) -------------------------------------
__device__ float  g_Q[BATCH*NH*SEQ*HD];
__device__ float  g_K[BATCH*NH*SEQ*HD];
__device__ float  g_V[BATCH*NH*SEQ*HD];
__device__ __half g_Xh[MTOT*HIDDEN];          // x in fp16
__device__ __half g_Ah[MTOT*HIDDEN];          // attention output in fp16
__device__ __half g_Wt[4][HIDDEN*HIDDEN];     // weights transposed [N][K], fp16

// ---------------- helpers -------------------------------------------------------
__device__ __forceinline__ uint32_t smem_u32(const void* p) {
    uint32_t a;
    asm("{ .reg .u64 t; cvta.to.shared.u64 t, %1; cvt.u32.u64 %0, t; }" : "=r"(a) : "l"(p));
    return a;
}
__device__ __forceinline__ float tf32r(float x) {
    uint32_t y;
    asm("cvt.rna.tf32.f32 %0, %1;" : "=r"(y) : "f"(x));
    return __uint_as_float(y);
}
__device__ __forceinline__ void cp16(uint32_t dst, const void* src) {
    asm volatile("cp.async.cg.shared.global [%0], [%1], 16;" :: "r"(dst), "l"(src) : "memory");
}
__device__ __forceinline__ void cp16z(uint32_t dst, const void* src, int srcsz) {
    asm volatile("cp.async.cg.shared.global [%0], [%1], 16, %2;"
                 :: "r"(dst), "l"(src), "r"(srcsz) : "memory");
}
#define CP_COMMIT() asm volatile("cp.async.commit_group;" ::: "memory")
#define CP_WAIT2()  asm volatile("cp.async.wait_group 2;" ::: "memory")
#define CP_WAIT0()  asm volatile("cp.async.wait_group 0;" ::: "memory")

__device__ __forceinline__ void mma_tf32(float* d, const uint32_t* a, const uint32_t* b) {
    asm volatile("mma.sync.aligned.m16n8k8.row.col.f32.tf32.tf32.f32 "
        "{%0,%1,%2,%3}, {%4,%5,%6,%7}, {%8,%9}, {%0,%1,%2,%3};"
        : "+f"(d[0]), "+f"(d[1]), "+f"(d[2]), "+f"(d[3])
        : "r"(a[0]), "r"(a[1]), "r"(a[2]), "r"(a[3]), "r"(b[0]), "r"(b[1]));
}
__device__ __forceinline__ void mma_f16(float* d, const uint32_t* a, const uint32_t* b) {
    asm volatile("mma.sync.aligned.m16n8k16.row.col.f32.f16.f16.f32 "
        "{%0,%1,%2,%3}, {%4,%5,%6,%7}, {%8,%9}, {%0,%1,%2,%3};"
        : "+f"(d[0]), "+f"(d[1]), "+f"(d[2]), "+f"(d[3])
        : "r"(a[0]), "r"(a[1]), "r"(a[2]), "r"(a[3]), "r"(b[0]), "r"(b[1]));
}

// ---------------- fp16 GEMM: 128x256 tile, 256 thr, 64x64 warp tile --------------
// A [M,K] f16 row-major; Wt [N,K] f16 row-major (= mma "col" B operand)
#define BM 128
#define BN 256
#define BK 32
#define STAGES 4
#define ASH 40                               // A stage row stride (halves)
#define BSH 40                               // B stage row stride (halves)
#define A_STAGE_H (BM*ASH)                   // 5120 halves
#define B_STAGE_H (BN*BSH)                   // 10240 halves
#define STAGE_H (A_STAGE_H + B_STAGE_H)      // 15360 halves = 30720 B
#define GEMM_SMEM (STAGES*STAGE_H*2)         // 122880 B

__global__ __launch_bounds__(256, 1) void gemm_f16_kernel(
    const __half* __restrict__ A,
    const __half* __restrict__ W0, const __half* __restrict__ W1, const __half* __restrict__ W2,
    const float* __restrict__ bias0, const float* __restrict__ bias1, const float* __restrict__ bias2,
    float* __restrict__ out0, float* __restrict__ out1, float* __restrict__ out2,
    int mode)
{
    extern __shared__ __half smh[];
    const int tid  = threadIdx.x;
    const int lane = tid & 31;
    const int wid  = tid >> 5;
    const int n0 = blockIdx.x * BN;
    const int m0 = blockIdx.y * BM;
    const int z  = blockIdx.z;

    const __half* W   = (z == 0) ? W0 : (z == 1) ? W1 : W2;
    const float* bias = (z == 0) ? bias0 : (z == 1) ? bias1 : bias2;
    float* out        = (z == 0) ? out0 : (z == 1) ? out1 : out2;

    const int wm = (wid & 1) * 64;
    const int wn = (wid >> 1) * 64;

    float d[4][8][4];
#pragma unroll
    for (int mi = 0; mi < 4; mi++)
#pragma unroll
        for (int ni = 0; ni < 8; ni++)
#pragma unroll
            for (int c = 0; c < 4; c++) d[mi][ni][c] = 0.f;

    const uint32_t sb = smem_u32(smh);

    auto load_stage = [&](int kt, int s) {
        const uint32_t a_off = sb + (uint32_t)(s * STAGE_H) * 2u;
        const uint32_t b_off = a_off + A_STAGE_H * 2u;
        const __half* Ag = A + (long)m0 * HIDDEN + kt * BK;
        const __half* Wg = W + (long)n0 * HIDDEN + kt * BK;
#pragma unroll
        for (int rep = 0; rep < 2; rep++) {
            int lin = rep * 256 + tid;          // 0..511
            int ar = lin >> 2, aq = lin & 3;    // 128 rows x 4 oct-chunks
            cp16(a_off + (uint32_t)(ar * ASH + aq * 8) * 2u,
                 Ag + (long)ar * HIDDEN + aq * 8);
        }
#pragma unroll
        for (int rep = 0; rep < 4; rep++) {
            int lin = rep * 256 + tid;          // 0..1023
            int br = lin >> 2, bq = lin & 3;    // 256 rows x 4 oct-chunks
            cp16(b_off + (uint32_t)(br * BSH + bq * 8) * 2u,
                 Wg + (long)br * HIDDEN + bq * 8);
        }
        CP_COMMIT();
    };

    load_stage(0, 0);
    load_stage(1, 1);
    load_stage(2, 2);

    const int lg = lane >> 2;
    const int lt = lane & 3;

    for (int kt = 0; kt < HIDDEN / BK; kt++) {
        const int s = kt & (STAGES - 1);
        CP_WAIT2();
        __syncthreads();
        if (kt + 3 < HIDDEN / BK) load_stage(kt + 3, (kt + 3) & (STAGES - 1));
        else CP_COMMIT();

        const __half* As = smh + s * STAGE_H;
        const __half* Bs = As + A_STAGE_H;

#pragma unroll
        for (int ks = 0; ks < 2; ks++) {        // 2 x k16 per BK=32
            const int kb = ks * 16;
            uint32_t a[4][4];
#pragma unroll
            for (int mi = 0; mi < 4; mi++) {
                const __half* ap = As + (wm + mi * 16 + lg) * ASH + kb + 2 * lt;
                a[mi][0] = *(const uint32_t*)(ap);
                a[mi][1] = *(const uint32_t*)(ap + 8 * ASH);
                a[mi][2] = *(const uint32_t*)(ap + 8);
                a[mi][3] = *(const uint32_t*)(ap + 8 * ASH + 8);
            }
#pragma unroll
            for (int ni = 0; ni < 8; ni++) {
                uint32_t bb[2];
                const __half* bp = Bs + (wn + ni * 8 + lg) * BSH + kb + 2 * lt;
                bb[0] = *(const uint32_t*)(bp);
                bb[1] = *(const uint32_t*)(bp + 8);
#pragma unroll
                for (int mi = 0; mi < 4; mi++)
                    mma_f16(d[mi][ni], a[mi], bb);
            }
        }
    }

    // epilogue: mode 0 -> rna-tf32-rounded fp32 Q/K/V; mode 1 -> raw fp32 output
#pragma unroll
    for (int mi = 0; mi < 4; mi++) {
#pragma unroll
        for (int rh = 0; rh < 2; rh++) {
            const int row = m0 + wm + mi * 16 + lg + rh * 8;
            const int bb = row >> 11;
            const int ss = row & (SEQ - 1);
#pragma unroll
            for (int ni = 0; ni < 8; ni++) {
                const int col = n0 + wn + ni * 8 + lt * 2;
                float2 v;
                v.x = d[mi][ni][rh * 2 + 0] + __ldg(&bias[col]);
                v.y = d[mi][ni][rh * 2 + 1] + __ldg(&bias[col + 1]);
                if (mode == 0) {
                    v.x = tf32r(v.x);
                    v.y = tf32r(v.y);
                    const int h  = col >> 6;
                    const int dd = col & 63;
                    *(float2*)&out[(((long)(bb * NH + h) * SEQ) + ss) * HD + dd] = v;
                } else {
                    *(float2*)&out[(long)row * HIDDEN + col] = v;
                }
            }
        }
    }
}

// ---------------- conversion kernels ----------------------------------------------
__global__ void cvtx_kernel(const float4* __restrict__ in, __half2* __restrict__ out, int n4) {
    int i = blockIdx.x * blockDim.x + threadIdx.x;
    if (i < n4) {
        float4 v = in[i];
        out[2 * i]     = __floats2half2_rn(v.x, v.y);
        out[2 * i + 1] = __floats2half2_rn(v.z, v.w);
    }
}
// transpose + convert: w [K][N] f32 -> wt [N][K] f16 ; z selects tensor
__global__ void cvtwT_kernel(const float* __restrict__ w0, const float* __restrict__ w1,
                             const float* __restrict__ w2, const float* __restrict__ w3,
                             __half* __restrict__ o0, __half* __restrict__ o1,
                             __half* __restrict__ o2, __half* __restrict__ o3) {
    __shared__ float t[32][33];
    const int z = blockIdx.z;
    const float* w = (z == 0) ? w0 : (z == 1) ? w1 : (z == 2) ? w2 : w3;
    __half* wt     = (z == 0) ? o0 : (z == 1) ? o1 : (z == 2) ? o2 : o3;
    const int tx = threadIdx.x, ty = threadIdx.y;
    const int n0 = blockIdx.x * 32, k0 = blockIdx.y * 32;
#pragma unroll
    for (int dy = 0; dy < 32; dy += 8)
        t[ty + dy][tx] = w[(long)(k0 + ty + dy) * HIDDEN + n0 + tx];
    __syncthreads();
#pragma unroll
    for (int dy = 0; dy < 32; dy += 8)
        wt[(long)(n0 + ty + dy) * HIDDEN + k0 + tx] = __float2half(t[tx][ty + dy]);
}

// ---------------- chunked attention (R12, fp16 output) -----------------------------
#define CH   160
#define SQ   68
#define SKN  68
#define SVC  72
#define SPC  164
#define SO   66
#define QS_OFF  0
#define KS_OFF  4352
#define VS_OFF  (KS_OFF + CH*SKN)
#define RED_OFF (VS_OFF + CH*SVC)
#define ATTN_FLOATS (RED_OFF + 128)
#define ATTN_SMEM (ATTN_FLOATS * 4)

__global__ __launch_bounds__(256, 2) void attn_mma_kernel(
    const float* __restrict__ Q, const float* __restrict__ K,
    const float* __restrict__ V, __half* __restrict__ O)
{
    extern __shared__ float sm[];
    float* Qs = sm + QS_OFF;
    float* Ks = sm + KS_OFF;
    float* Vs = sm + VS_OFF;
    float* red = sm + RED_OFF;

    const int q0 = blockIdx.x * QB;
    const int h  = blockIdx.y;
    const int b  = blockIdx.z;
    const int tid = threadIdx.x;
    const long base = ((long)(b * NH + h)) * SEQ * HD;
    const float* Kb = K + base;
    const float* Vb = V + base;
    const float* Qb = Q + base;
    const int j0 = q0 - WIN;

    const uint32_t sb = smem_u32(sm);
    const int lane = tid & 31;
    const int wid  = tid >> 5;
    const int lg = lane >> 2;
    const int lt = lane & 3;
    const int wm = (wid & 3) * 16;
    const int khalf = wid >> 2;
    const int wn = khalf * 80;
    const float scale = 0.125f;

    // Q tile via cp.async: 64 rows x 16 quads
    {
#pragma unroll
        for (int rep = 0; rep < 4; rep++) {
            const int idx = rep * 256 + tid;
            const int r = idx >> 4;
            const int q = idx & 15;
            cp16(sb + (uint32_t)(QS_OFF + r * SQ + q * 4) * 4u,
                 Qb + (long)(q0 + r) * HD + q * 4);
        }
        CP_COMMIT();
    }

    float o[8][4];
#pragma unroll
    for (int nt = 0; nt < 8; nt++) { o[nt][0] = 0.f; o[nt][1] = 0.f; o[nt][2] = 0.f; o[nt][3] = 0.f; }
    float sum0 = 0.f, sum1 = 0.f;

    const int r0 = q0 + wm + lg;
    const int r1 = r0 + 8;
    const int lo0 = ((r0 - WIN > 0) ? r0 - WIN : 0) - j0;
    const int hi0 = ((r0 + WIN < SEQ - 1) ? r0 + WIN : SEQ - 1) - j0;
    const int lo1 = ((r1 - WIN > 0) ? r1 - WIN : 0) - j0;
    const int hi1 = ((r1 + WIN < SEQ - 1) ? r1 + WIN : SEQ - 1) - j0;

    uint32_t a[8][4];
    bool afrag_loaded = false;

#pragma unroll
    for (int ch = 0; ch < 2; ch++) {
        const int cb = ch * CH;

        {
            const int rb = tid >> 4;
            const int cq = (tid & 15) << 2;
#pragma unroll
            for (int r10 = 0; r10 < 10; r10++) {
                const int jj = r10 * 16 + rb;
                const int j  = j0 + cb + jj;
                const int ok = (j >= 0 && j < SEQ) ? 16 : 0;
                cp16z(sb + (uint32_t)(KS_OFF + jj * SKN + cq) * 4u, Kb + (long)j * HD + cq, ok);
                cp16z(sb + (uint32_t)(VS_OFF + jj * SVC + cq) * 4u, Vb + (long)j * HD + cq, ok);
            }
            CP_COMMIT();
        }
        CP_WAIT0();
        __syncthreads();

        if (!afrag_loaded) {
            afrag_loaded = true;
#pragma unroll
            for (int k8 = 0; k8 < 8; k8++) {
                const float* ap = Qs + (wm + lg) * SQ + k8 * 8 + lt;
                a[k8][0] = __float_as_uint(ap[0]);
                a[k8][1] = __float_as_uint(ap[8 * SQ]);
                a[k8][2] = __float_as_uint(ap[4]);
                a[k8][3] = __float_as_uint(ap[8 * SQ + 4]);
            }
        }

        float c[10][4];
#pragma unroll
        for (int nt = 0; nt < 10; nt++) {
            c[nt][0] = 0.f; c[nt][1] = 0.f; c[nt][2] = 0.f; c[nt][3] = 0.f;
            const int key = wn + nt * 8 + lg;
            const float* kp = Ks + key * SKN + lt;
#pragma unroll
            for (int k8 = 0; k8 < 8; k8++) {
                uint32_t bb[2];
                bb[0] = __float_as_uint(kp[k8 * 8]);
                bb[1] = __float_as_uint(kp[k8 * 8 + 4]);
                mma_tf32(c[nt], a[k8], bb);
            }
        }

#pragma unroll
        for (int nt = 0; nt < 10; nt++) {
            const int jw = cb + wn + nt * 8 + 2 * lt;
            float p0 = (jw     >= lo0 && jw     <= hi0) ? tf32r(__expf(c[nt][0] * scale)) : 0.f;
            float p1 = (jw + 1 >= lo0 && jw + 1 <= hi0) ? tf32r(__expf(c[nt][1] * scale)) : 0.f;
            float p2 = (jw     >= lo1 && jw     <= hi1) ? tf32r(__expf(c[nt][2] * scale)) : 0.f;
            float p3 = (jw + 1 >= lo1 && jw + 1 <= hi1) ? tf32r(__expf(c[nt][3] * scale)) : 0.f;
            c[nt][0] = p0; c[nt][1] = p1; c[nt][2] = p2; c[nt][3] = p3;
            sum0 += p0 + p1;
            sum1 += p2 + p3;
        }

        __syncthreads();

        float* Ps = Ks;
#pragma unroll
        for (int nt = 0; nt < 10; nt++) {
            const int col = wn + nt * 8 + 2 * lt;
            *(float2*)&Ps[(wm + lg) * SPC + col]     = make_float2(c[nt][0], c[nt][1]);
            *(float2*)&Ps[(wm + lg + 8) * SPC + col] = make_float2(c[nt][2], c[nt][3]);
        }
        __syncthreads();

#pragma unroll
        for (int k8 = 0; k8 < 10; k8++) {
            const int kk = wn + k8 * 8;
            uint32_t a2[4];
            const float* ap = Ps + (wm + lg) * SPC + kk + lt;
            a2[0] = __float_as_uint(ap[0]);
            a2[1] = __float_as_uint(ap[8 * SPC]);
            a2[2] = __float_as_uint(ap[4]);
            a2[3] = __float_as_uint(ap[8 * SPC + 4]);
#pragma unroll
            for (int nt = 0; nt < 8; nt++) {
                uint32_t bb[2];
                const float* bp = Vs + (kk + lt) * SVC + nt * 8 + lg;
                bb[0] = __float_as_uint(bp[0]);
                bb[1] = __float_as_uint(bp[4 * SVC]);
                mma_tf32(o[nt], a2, bb);
            }
        }
        __syncthreads();
    }

    sum0 += __shfl_xor_sync(0xffffffffu, sum0, 1);
    sum0 += __shfl_xor_sync(0xffffffffu, sum0, 2);
    sum1 += __shfl_xor_sync(0xffffffffu, sum1, 1);
    sum1 += __shfl_xor_sync(0xffffffffu, sum1, 2);
    if (lt == 0) {
        red[khalf * 64 + wm + lg]     = sum0;
        red[khalf * 64 + wm + lg + 8] = sum1;
    }

    float* obuf = Qs;
    if (khalf == 0) {
#pragma unroll
        for (int nt = 0; nt < 8; nt++) {
            const int col = nt * 8 + 2 * lt;
            *(float2*)&obuf[(wm + lg) * SO + col]     = make_float2(o[nt][0], o[nt][1]);
            *(float2*)&obuf[(wm + lg + 8) * SO + col] = make_float2(o[nt][2], o[nt][3]);
        }
    }
    __syncthreads();
    if (khalf == 1) {
        const float inv0 = 1.f / (red[wm + lg] + red[64 + wm + lg]);
        const float inv1 = 1.f / (red[wm + lg + 8] + red[64 + wm + lg + 8]);
        const long ob0 = ((long)(b * SEQ + r0)) * HIDDEN + h * HD;
        const long ob1 = ((long)(b * SEQ + r1)) * HIDDEN + h * HD;
#pragma unroll
        for (int nt = 0; nt < 8; nt++) {
            const int col = nt * 8 + 2 * lt;
            float2 u0 = *(const float2*)&obuf[(wm + lg) * SO + col];
            float2 u1 = *(const float2*)&obuf[(wm + lg + 8) * SO + col];
            *(__half2*)&O[ob0 + col] = __floats2half2_rn((o[nt][0] + u0.x) * inv0,
                                                         (o[nt][1] + u0.y) * inv0);
            *(__half2*)&O[ob1 + col] = __floats2half2_rn((o[nt][2] + u1.x) * inv1,
                                                         (o[nt][3] + u1.y) * inv1);
        }
    }
}

// ---------------- launcher --------------------------------------------------------
extern "C" void kernel_launch(void* const* d_in, const int* in_sizes, int n_in,
                              void* d_out, int out_size)
{
    const float* x  = (const float*)d_in[0];
    const float* wq = (const float*)d_in[1];
    const float* bq = (const float*)d_in[2];
    const float* wk = (const float*)d_in[3];
    const float* bk = (const float*)d_in[4];
    const float* wv = (const float*)d_in[5];
    const float* bv = (const float*)d_in[6];
    const float* wo = (const float*)d_in[7];
    const float* bo = (const float*)d_in[8];

    float *gq, *gk, *gv;
    __half *gxh, *gah, *gwt;
    cudaGetSymbolAddress((void**)&gq,  g_Q);
    cudaGetSymbolAddress((void**)&gk,  g_K);
    cudaGetSymbolAddress((void**)&gv,  g_V);
    cudaGetSymbolAddress((void**)&gxh, g_Xh);
    cudaGetSymbolAddress((void**)&gah, g_Ah);
    cudaGetSymbolAddress((void**)&gwt, g_Wt);
    __half* gw0 = gwt;
    __half* gw1 = gwt + (size_t)HIDDEN * HIDDEN;
    __half* gw2 = gwt + (size_t)2 * HIDDEN * HIDDEN;
    __half* gw3 = gwt + (size_t)3 * HIDDEN * HIDDEN;

    cudaFuncSetAttribute(gemm_f16_kernel,
                         cudaFuncAttributeMaxDynamicSharedMemorySize, GEMM_SMEM);
    cudaFuncSetAttribute(attn_mma_kernel,
                         cudaFuncAttributeMaxDynamicSharedMemorySize, ATTN_SMEM);

    const int n4a = MTOT * HIDDEN / 4;

    // x -> fp16
    cvtx_kernel<<<(n4a + 255) / 256, 256>>>((const float4*)x, (__half2*)gxh, n4a);
    // weights -> transposed fp16
    {
        dim3 g(HIDDEN / 32, HIDDEN / 32, 4), b(32, 8);
        cvtwT_kernel<<<g, b>>>(wq, wk, wv, wo, gw0, gw1, gw2, gw3);
    }
    {   // fused QKV projections (fp16 operands, fp32 accum)
        dim3 g(HIDDEN / BN, MTOT / BM, 3);
        gemm_f16_kernel<<<g, 256, GEMM_SMEM>>>(gxh, gw0, gw1, gw2,
                                               bq, bk, bv, gq, gk, gv, 0);
    }
    {   // chunked MMA attention -> fp16 output
        dim3 ga(SEQ / QB, NH, BATCH);
        attn_mma_kernel<<<ga, 256, ATTN_SMEM>>>(gq, gk, gv, gah);
    }
    {   // output projection
        dim3 g(HIDDEN / BN, MTOT / BM, 1);
        gemm_f16_kernel<<<g, 256, GEMM_SMEM>>>(gah, gw3, gw3, gw3,
                                               bo, bo, bo, (float*)d_out,
                                               (float*)d_out, (float*)d_out, 1);
    }
}

// round 16
// speedup vs baseline: 1.5492x; 1.0110x over previous
#include <cuda_runtime.h>
#include <cuda_fp16.h>
#include <cstdint>
#include <math.h>

#define HIDDEN 1024
#define NH     16
#define HD     64
#define SEQ    2048
#define BATCH  2
#define MTOT   (BATCH*SEQ)   // 4096
#define WIN    128
#define QB     64

// ---------------- scratch (device globals) -------------------------------------
__device__ __half g_Qh[BATCH*NH*SEQ*HD];      // [b,h,s,d] fp16
__device__ __half g_Kh[BATCH*NH*SEQ*HD];      // [b,h,s,d] fp16
__device__ float  g_V [BATCH*NH*SEQ*HD];      // [b,h,s,d] fp32 (tf32-rounded)
__device__ __half g_Xh[MTOT*HIDDEN];          // x in fp16
__device__ __half g_Ah[MTOT*HIDDEN];          // attention output in fp16
__device__ __half g_Wt[4][HIDDEN*HIDDEN];     // weights transposed [N][K], fp16

// ---------------- helpers -------------------------------------------------------
__device__ __forceinline__ uint32_t smem_u32(const void* p) {
    uint32_t a;
    asm("{ .reg .u64 t; cvta.to.shared.u64 t, %1; cvt.u32.u64 %0, t; }" : "=r"(a) : "l"(p));
    return a;
}
__device__ __forceinline__ float tf32r(float x) {
    uint32_t y;
    asm("cvt.rna.tf32.f32 %0, %1;" : "=r"(y) : "f"(x));
    return __uint_as_float(y);
}
__device__ __forceinline__ void cp16(uint32_t dst, const void* src) {
    asm volatile("cp.async.cg.shared.global [%0], [%1], 16;" :: "r"(dst), "l"(src) : "memory");
}
__device__ __forceinline__ void cp16z(uint32_t dst, const void* src, int srcsz) {
    asm volatile("cp.async.cg.shared.global [%0], [%1], 16, %2;"
                 :: "r"(dst), "l"(src), "r"(srcsz) : "memory");
}
#define CP_COMMIT() asm volatile("cp.async.commit_group;" ::: "memory")
#define CP_WAIT2()  asm volatile("cp.async.wait_group 2;" ::: "memory")
#define CP_WAIT0()  asm volatile("cp.async.wait_group 0;" ::: "memory")

__device__ __forceinline__ void mma_f16(float* d, const uint32_t* a, const uint32_t* b) {
    asm volatile("mma.sync.aligned.m16n8k16.row.col.f32.f16.f16.f32 "
        "{%0,%1,%2,%3}, {%4,%5,%6,%7}, {%8,%9}, {%0,%1,%2,%3};"
        : "+f"(d[0]), "+f"(d[1]), "+f"(d[2]), "+f"(d[3])
        : "r"(a[0]), "r"(a[1]), "r"(a[2]), "r"(a[3]), "r"(b[0]), "r"(b[1]));
}
__device__ __forceinline__ void mma_tf32(float* d, const uint32_t* a, const uint32_t* b) {
    asm volatile("mma.sync.aligned.m16n8k8.row.col.f32.tf32.tf32.f32 "
        "{%0,%1,%2,%3}, {%4,%5,%6,%7}, {%8,%9}, {%0,%1,%2,%3};"
        : "+f"(d[0]), "+f"(d[1]), "+f"(d[2]), "+f"(d[3])
        : "r"(a[0]), "r"(a[1]), "r"(a[2]), "r"(a[3]), "r"(b[0]), "r"(b[1]));
}

// ---------------- fp16 GEMM: 128x256 tile, 256 thr, 64x64 warp tile --------------
#define BM 128
#define BN 256
#define BK 32
#define STAGES 4
#define ASH 40
#define BSH 40
#define A_STAGE_H (BM*ASH)
#define B_STAGE_H (BN*BSH)
#define STAGE_H (A_STAGE_H + B_STAGE_H)
#define GEMM_SMEM (STAGES*STAGE_H*2)         // 122880 B

__global__ __launch_bounds__(256, 1) void gemm_f16_kernel(
    const __half* __restrict__ A,
    const __half* __restrict__ W0, const __half* __restrict__ W1, const __half* __restrict__ W2,
    const float* __restrict__ bias0, const float* __restrict__ bias1, const float* __restrict__ bias2,
    void* __restrict__ out0, void* __restrict__ out1, void* __restrict__ out2,
    int mode)
{
    extern __shared__ __half smh[];
    const int tid  = threadIdx.x;
    const int lane = tid & 31;
    const int wid  = tid >> 5;
    const int n0 = blockIdx.x * BN;
    const int m0 = blockIdx.y * BM;
    const int z  = blockIdx.z;

    const __half* W   = (z == 0) ? W0 : (z == 1) ? W1 : W2;
    const float* bias = (z == 0) ? bias0 : (z == 1) ? bias1 : bias2;
    void* out         = (z == 0) ? out0 : (z == 1) ? out1 : out2;

    const int wm = (wid & 1) * 64;
    const int wn = (wid >> 1) * 64;

    float d[4][8][4];
#pragma unroll
    for (int mi = 0; mi < 4; mi++)
#pragma unroll
        for (int ni = 0; ni < 8; ni++)
#pragma unroll
            for (int c = 0; c < 4; c++) d[mi][ni][c] = 0.f;

    const uint32_t sb = smem_u32(smh);

    auto load_stage = [&](int kt, int s) {
        const uint32_t a_off = sb + (uint32_t)(s * STAGE_H) * 2u;
        const uint32_t b_off = a_off + A_STAGE_H * 2u;
        const __half* Ag = A + (long)m0 * HIDDEN + kt * BK;
        const __half* Wg = W + (long)n0 * HIDDEN + kt * BK;
#pragma unroll
        for (int rep = 0; rep < 2; rep++) {
            int lin = rep * 256 + tid;
            int ar = lin >> 2, aq = lin & 3;
            cp16(a_off + (uint32_t)(ar * ASH + aq * 8) * 2u,
                 Ag + (long)ar * HIDDEN + aq * 8);
        }
#pragma unroll
        for (int rep = 0; rep < 4; rep++) {
            int lin = rep * 256 + tid;
            int br = lin >> 2, bq = lin & 3;
            cp16(b_off + (uint32_t)(br * BSH + bq * 8) * 2u,
                 Wg + (long)br * HIDDEN + bq * 8);
        }
        CP_COMMIT();
    };

    load_stage(0, 0);
    load_stage(1, 1);
    load_stage(2, 2);

    const int lg = lane >> 2;
    const int lt = lane & 3;

    for (int kt = 0; kt < HIDDEN / BK; kt++) {
        const int s = kt & (STAGES - 1);
        CP_WAIT2();
        __syncthreads();
        if (kt + 3 < HIDDEN / BK) load_stage(kt + 3, (kt + 3) & (STAGES - 1));
        else CP_COMMIT();

        const __half* As = smh + s * STAGE_H;
        const __half* Bs = As + A_STAGE_H;

#pragma unroll
        for (int ks = 0; ks < 2; ks++) {
            const int kb = ks * 16;
            uint32_t a[4][4];
#pragma unroll
            for (int mi = 0; mi < 4; mi++) {
                const __half* ap = As + (wm + mi * 16 + lg) * ASH + kb + 2 * lt;
                a[mi][0] = *(const uint32_t*)(ap);
                a[mi][1] = *(const uint32_t*)(ap + 8 * ASH);
                a[mi][2] = *(const uint32_t*)(ap + 8);
                a[mi][3] = *(const uint32_t*)(ap + 8 * ASH + 8);
            }
#pragma unroll
            for (int ni = 0; ni < 8; ni++) {
                uint32_t bb[2];
                const __half* bp = Bs + (wn + ni * 8 + lg) * BSH + kb + 2 * lt;
                bb[0] = *(const uint32_t*)(bp);
                bb[1] = *(const uint32_t*)(bp + 8);
#pragma unroll
                for (int mi = 0; mi < 4; mi++)
                    mma_f16(d[mi][ni], a[mi], bb);
            }
        }
    }

    // epilogue:
    //   mode 0, z<2 : fp16 Q/K [b,h,s,d]
    //   mode 0, z==2: fp32 tf32-rounded V [b,h,s,d]
    //   mode 1      : raw fp32 row-major
#pragma unroll
    for (int mi = 0; mi < 4; mi++) {
#pragma unroll
        for (int rh = 0; rh < 2; rh++) {
            const int row = m0 + wm + mi * 16 + lg + rh * 8;
            const int bb = row >> 11;
            const int ss = row & (SEQ - 1);
#pragma unroll
            for (int ni = 0; ni < 8; ni++) {
                const int col = n0 + wn + ni * 8 + lt * 2;
                float2 v;
                v.x = d[mi][ni][rh * 2 + 0] + __ldg(&bias[col]);
                v.y = d[mi][ni][rh * 2 + 1] + __ldg(&bias[col + 1]);
                if (mode == 0) {
                    const int h  = col >> 6;
                    const int dd = col & 63;
                    const long off = (((long)(bb * NH + h) * SEQ) + ss) * HD + dd;
                    if (z < 2) {
                        *(__half2*)&((__half*)out)[off] = __floats2half2_rn(v.x, v.y);
                    } else {
                        v.x = tf32r(v.x);
                        v.y = tf32r(v.y);
                        *(float2*)&((float*)out)[off] = v;
                    }
                } else {
                    *(float2*)&((float*)out)[(long)row * HIDDEN + col] = v;
                }
            }
        }
    }
}

// ---------------- conversion kernels ----------------------------------------------
__global__ void cvtx_kernel(const float4* __restrict__ in, __half2* __restrict__ out, int n4) {
    int i = blockIdx.x * blockDim.x + threadIdx.x;
    if (i < n4) {
        float4 v = in[i];
        out[2 * i]     = __floats2half2_rn(v.x, v.y);
        out[2 * i + 1] = __floats2half2_rn(v.z, v.w);
    }
}
__global__ void cvtwT_kernel(const float* __restrict__ w0, const float* __restrict__ w1,
                             const float* __restrict__ w2, const float* __restrict__ w3,
                             __half* __restrict__ o0, __half* __restrict__ o1,
                             __half* __restrict__ o2, __half* __restrict__ o3) {
    __shared__ float t[32][33];
    const int z = blockIdx.z;
    const float* w = (z == 0) ? w0 : (z == 1) ? w1 : (z == 2) ? w2 : w3;
    __half* wt     = (z == 0) ? o0 : (z == 1) ? o1 : (z == 2) ? o2 : o3;
    const int tx = threadIdx.x, ty = threadIdx.y;
    const int n0 = blockIdx.x * 32, k0 = blockIdx.y * 32;
#pragma unroll
    for (int dy = 0; dy < 32; dy += 8)
        t[ty + dy][tx] = w[(long)(k0 + ty + dy) * HIDDEN + n0 + tx];
    __syncthreads();
#pragma unroll
    for (int dy = 0; dy < 32; dy += 8)
        wt[(long)(n0 + ty + dy) * HIDDEN + k0 + tx] = __float2half(t[tx][ty + dy]);
}

// ---------------- attention: fp16 QK (k16 mma) + fp32/tf32 PV ---------------------
#define CH   160
#define SQH  72                               // Q smem stride, halves (64 + 8 pad)
#define SKH  72                               // K smem stride, halves (64 + 8 pad)
#define SVC  72                               // V smem stride, floats
#define SPC  164                              // P smem stride, floats
#define SO   66                               // obuf stride, floats
// half-unit offsets
#define QS_OFFH  0                            // Q: 64*72 = 4608 h
#define KP_OFFH  4608                         // K fp16 [160][72]=11520h, aliased by
                                              //   P fp32 [64][164]=20992h (region 20992h)
#define VS_OFFF  12800                        // float offset: (4608+20992)/2
#define RED_OFFF (VS_OFFF + CH*SVC)           // 24320 floats
#define ATTN_SMEM ((RED_OFFF + 128) * 4)      // 97792 B

__global__ __launch_bounds__(256, 2) void attn_hyb_kernel(
    const __half* __restrict__ Q, const __half* __restrict__ K,
    const float* __restrict__ V, __half* __restrict__ O)
{
    extern __shared__ __half smh[];
    __half* Qs  = smh + QS_OFFH;              // [64][72] fp16
    __half* Ks  = smh + KP_OFFH;              // [160][72] fp16
    float*  Ps  = (float*)(smh + KP_OFFH);    // [64][164] fp32 (aliases Ks)
    float*  Vs  = (float*)smh + VS_OFFF;      // [160][72] fp32
    float*  red = (float*)smh + RED_OFFF;     // [2][64]

    const int q0 = blockIdx.x * QB;
    const int h  = blockIdx.y;
    const int b  = blockIdx.z;
    const int tid = threadIdx.x;
    const long base = ((long)(b * NH + h)) * SEQ * HD;
    const __half* Kb = K + base;
    const float*  Vb = V + base;
    const __half* Qb = Q + base;
    const int j0 = q0 - WIN;

    const uint32_t sb = smem_u32(smh);
    const int lane = tid & 31;
    const int wid  = tid >> 5;
    const int lg = lane >> 2;
    const int lt = lane & 3;
    const int wm = (wid & 3) * 16;
    const int khalf = wid >> 2;
    const int wn = khalf * 80;
    const float scale = 0.125f;

    // ---- Q tile fp16: 64 rows x 8 chunks of 16B, stride 72 ----
    {
#pragma unroll
        for (int rep = 0; rep < 2; rep++) {
            const int idx = rep * 256 + tid;
            const int r = idx >> 3, c = idx & 7;
            cp16(sb + (uint32_t)(QS_OFFH + r * SQH + c * 8) * 2u,
                 Qb + (long)(q0 + r) * HD + c * 8);
        }
        CP_COMMIT();
    }

    float o[8][4];
#pragma unroll
    for (int nt = 0; nt < 8; nt++) { o[nt][0] = 0.f; o[nt][1] = 0.f; o[nt][2] = 0.f; o[nt][3] = 0.f; }
    float sum0 = 0.f, sum1 = 0.f;

    const int r0 = q0 + wm + lg;
    const int r1 = r0 + 8;
    const int lo0 = ((r0 - WIN > 0) ? r0 - WIN : 0) - j0;
    const int hi0 = ((r0 + WIN < SEQ - 1) ? r0 + WIN : SEQ - 1) - j0;
    const int lo1 = ((r1 - WIN > 0) ? r1 - WIN : 0) - j0;
    const int hi1 = ((r1 + WIN < SEQ - 1) ? r1 + WIN : SEQ - 1) - j0;

    uint32_t a[4][4];
    bool afrag_loaded = false;

#pragma unroll
    for (int ch = 0; ch < 2; ch++) {
        const int cb = ch * CH;

        // ---- K chunk fp16 [160][72] + V chunk fp32 [160][72] ----
        {
#pragma unroll
            for (int rep = 0; rep < 5; rep++) {
                const int r = rep * 32 + (tid >> 3);
                const int c = tid & 7;
                const int j = j0 + cb + r;
                const int ok = (j >= 0 && j < SEQ) ? 16 : 0;
                cp16z(sb + (uint32_t)(KP_OFFH + r * SKH + c * 8) * 2u,
                      Kb + (long)j * HD + c * 8, ok);
            }
            const int rb = tid >> 4;
            const int cq = (tid & 15) << 2;
#pragma unroll
            for (int r10 = 0; r10 < 10; r10++) {
                const int jj = r10 * 16 + rb;
                const int j  = j0 + cb + jj;
                const int ok = (j >= 0 && j < SEQ) ? 16 : 0;
                cp16z(sb + (uint32_t)(VS_OFFF + jj * SVC + cq) * 4u,
                      Vb + (long)j * HD + cq, ok);
            }
            CP_COMMIT();
        }
        CP_WAIT0();
        __syncthreads();

        if (!afrag_loaded) {
            afrag_loaded = true;
#pragma unroll
            for (int k16 = 0; k16 < 4; k16++) {
                const __half* ap = Qs + (wm + lg) * SQH + k16 * 16 + 2 * lt;
                a[k16][0] = *(const uint32_t*)(ap);
                a[k16][1] = *(const uint32_t*)(ap + 8 * SQH);
                a[k16][2] = *(const uint32_t*)(ap + 8);
                a[k16][3] = *(const uint32_t*)(ap + 8 * SQH + 8);
            }
        }

        // ---- S = Q @ K^T : fp16, 4 x k16 ----
        float c[10][4];
#pragma unroll
        for (int nt = 0; nt < 10; nt++) { c[nt][0] = 0.f; c[nt][1] = 0.f; c[nt][2] = 0.f; c[nt][3] = 0.f; }
#pragma unroll
        for (int k16 = 0; k16 < 4; k16++) {
            const int kb = k16 * 16;
#pragma unroll
            for (int nt = 0; nt < 10; nt++) {
                uint32_t bb[2];
                const __half* bp = Ks + (wn + nt * 8 + lg) * SKH + kb + 2 * lt;
                bb[0] = *(const uint32_t*)(bp);
                bb[1] = *(const uint32_t*)(bp + 8);
                mma_f16(c[nt], a[k16], bb);
            }
        }

        // ---- mask + exp + partial sums ----
#pragma unroll
        for (int nt = 0; nt < 10; nt++) {
            const int jw = cb + wn + nt * 8 + 2 * lt;
            float p0 = (jw     >= lo0 && jw     <= hi0) ? tf32r(__expf(c[nt][0] * scale)) : 0.f;
            float p1 = (jw + 1 >= lo0 && jw + 1 <= hi0) ? tf32r(__expf(c[nt][1] * scale)) : 0.f;
            float p2 = (jw     >= lo1 && jw     <= hi1) ? tf32r(__expf(c[nt][2] * scale)) : 0.f;
            float p3 = (jw + 1 >= lo1 && jw + 1 <= hi1) ? tf32r(__expf(c[nt][3] * scale)) : 0.f;
            c[nt][0] = p0; c[nt][1] = p1; c[nt][2] = p2; c[nt][3] = p3;
            sum0 += p0 + p1;
            sum1 += p2 + p3;
        }

        __syncthreads();   // done reading Ks -> safe to alias with P (fp32)

#pragma unroll
        for (int nt = 0; nt < 10; nt++) {
            const int col = wn + nt * 8 + 2 * lt;
            *(float2*)&Ps[(wm + lg) * SPC + col]     = make_float2(c[nt][0], c[nt][1]);
            *(float2*)&Ps[(wm + lg + 8) * SPC + col] = make_float2(c[nt][2], c[nt][3]);
        }
        __syncthreads();

        // ---- O += P @ V : tf32, 10 x k8 per 80-key half ----
#pragma unroll
        for (int k8 = 0; k8 < 10; k8++) {
            const int kk = wn + k8 * 8;
            uint32_t a2[4];
            const float* ap = Ps + (wm + lg) * SPC + kk + lt;
            a2[0] = __float_as_uint(ap[0]);
            a2[1] = __float_as_uint(ap[8 * SPC]);
            a2[2] = __float_as_uint(ap[4]);
            a2[3] = __float_as_uint(ap[8 * SPC + 4]);
#pragma unroll
            for (int nt = 0; nt < 8; nt++) {
                uint32_t bb[2];
                const float* bp = Vs + (kk + lt) * SVC + nt * 8 + lg;
                bb[0] = __float_as_uint(bp[0]);
                bb[1] = __float_as_uint(bp[4 * SVC]);
                mma_tf32(o[nt], a2, bb);
            }
        }
        __syncthreads();
    }

    // ---- reduce sums, combine split-K halves, normalize, write fp16 ----
    sum0 += __shfl_xor_sync(0xffffffffu, sum0, 1);
    sum0 += __shfl_xor_sync(0xffffffffu, sum0, 2);
    sum1 += __shfl_xor_sync(0xffffffffu, sum1, 1);
    sum1 += __shfl_xor_sync(0xffffffffu, sum1, 2);
    if (lt == 0) {
        red[khalf * 64 + wm + lg]     = sum0;
        red[khalf * 64 + wm + lg + 8] = sum1;
    }

    float* obuf = Ps;   // alias (done with P)
    if (khalf == 0) {
#pragma unroll
        for (int nt = 0; nt < 8; nt++) {
            const int col = nt * 8 + 2 * lt;
            *(float2*)&obuf[(wm + lg) * SO + col]     = make_float2(o[nt][0], o[nt][1]);
            *(float2*)&obuf[(wm + lg + 8) * SO + col] = make_float2(o[nt][2], o[nt][3]);
        }
    }
    __syncthreads();
    if (khalf == 1) {
        const float inv0 = 1.f / (red[wm + lg] + red[64 + wm + lg]);
        const float inv1 = 1.f / (red[wm + lg + 8] + red[64 + wm + lg + 8]);
        const long ob0 = ((long)(b * SEQ + r0)) * HIDDEN + h * HD;
        const long ob1 = ((long)(b * SEQ + r1)) * HIDDEN + h * HD;
#pragma unroll
        for (int nt = 0; nt < 8; nt++) {
            const int col = nt * 8 + 2 * lt;
            float2 u0 = *(const float2*)&obuf[(wm + lg) * SO + col];
            float2 u1 = *(const float2*)&obuf[(wm + lg + 8) * SO + col];
            *(__half2*)&O[ob0 + col] = __floats2half2_rn((o[nt][0] + u0.x) * inv0,
                                                         (o[nt][1] + u0.y) * inv0);
            *(__half2*)&O[ob1 + col] = __floats2half2_rn((o[nt][2] + u1.x) * inv1,
                                                         (o[nt][3] + u1.y) * inv1);
        }
    }
}

// ---------------- launcher --------------------------------------------------------
extern "C" void kernel_launch(void* const* d_in, const int* in_sizes, int n_in,
                              void* d_out, int out_size)
{
    const float* x  = (const float*)d_in[0];
    const float* wq = (const float*)d_in[1];
    const float* bq = (const float*)d_in[2];
    const float* wk = (const float*)d_in[3];
    const float* bk = (const float*)d_in[4];
    const float* wv = (const float*)d_in[5];
    const float* bv = (const float*)d_in[6];
    const float* wo = (const float*)d_in[7];
    const float* bo = (const float*)d_in[8];

    __half *gq, *gk, *gxh, *gah, *gwt;
    float *gv;
    cudaGetSymbolAddress((void**)&gq,  g_Qh);
    cudaGetSymbolAddress((void**)&gk,  g_Kh);
    cudaGetSymbolAddress((void**)&gv,  g_V);
    cudaGetSymbolAddress((void**)&gxh, g_Xh);
    cudaGetSymbolAddress((void**)&gah, g_Ah);
    cudaGetSymbolAddress((void**)&gwt, g_Wt);
    __half* gw0 = gwt;
    __half* gw1 = gwt + (size_t)HIDDEN * HIDDEN;
    __half* gw2 = gwt + (size_t)2 * HIDDEN * HIDDEN;
    __half* gw3 = gwt + (size_t)3 * HIDDEN * HIDDEN;

    cudaFuncSetAttribute(gemm_f16_kernel,
                         cudaFuncAttributeMaxDynamicSharedMemorySize, GEMM_SMEM);
    cudaFuncSetAttribute(attn_hyb_kernel,
                         cudaFuncAttributeMaxDynamicSharedMemorySize, ATTN_SMEM);

    const int n4a = MTOT * HIDDEN / 4;

    cvtx_kernel<<<(n4a + 255) / 256, 256>>>((const float4*)x, (__half2*)gxh, n4a);
    {
        dim3 g(HIDDEN / 32, HIDDEN / 32, 4), b(32, 8);
        cvtwT_kernel<<<g, b>>>(wq, wk, wv, wo, gw0, gw1, gw2, gw3);
    }
    {   // fused QKV projections -> fp16 Q/K, fp32 V
        dim3 g(HIDDEN / BN, MTOT / BM, 3);
        gemm_f16_kernel<<<g, 256, GEMM_SMEM>>>(gxh, gw0, gw1, gw2,
                                               bq, bk, bv, gq, gk, gv, 0);
    }
    {   // hybrid attention (fp16 QK, tf32 PV) -> fp16 output
        dim3 ga(SEQ / QB, NH, BATCH);
        attn_hyb_kernel<<<ga, 256, ATTN_SMEM>>>(gq, gk, gv, gah);
    }
    {   // output projection -> fp32 d_out
        dim3 g(HIDDEN / BN, MTOT / BM, 1);
        gemm_f16_kernel<<<g, 256, GEMM_SMEM>>>(gah, gw3, gw3, gw3,
                                               bo, bo, bo, d_out, d_out, d_out, 1);
    }
}